// round 1
// baseline (speedup 1.0000x reference)
#include <cuda_runtime.h>

#define FULLMASK 0xffffffffu

// ---------------- scratch (static __device__, no allocations) ----------------
static __device__ unsigned int       g_u[86016];        // orderable score bits per anchor
static __device__ unsigned char      g_label[86016];    // argmax class per anchor
static __device__ unsigned int       g_hist[3 * 65536]; // 16-bit histograms per level
static __device__ int                g_B[3];            // boundary bin per level
static __device__ int                g_candcnt[3];
static __device__ unsigned long long g_cand[3 * 4096];  // (u<<32)|(~local_idx)
static __device__ unsigned long long g_nkey[3008];      // global NMS sort keys
static __device__ float4             g_nbox[3008];      // class-offset boxes (concat order)
static __device__ unsigned char      g_nvalid[3008];
static __device__ int                g_sorder[3008];    // sorted rank -> concat idx
static __device__ float4             g_sbox[3008];      // sorted boxes
static __device__ float              g_sarea[3008];
static __device__ unsigned long long g_validw[48];      // valid bits in sorted order
static __device__ unsigned long long g_supp[3008 * 48]; // suppression bit matrix

__device__ __forceinline__ float sigf(float x) {
    float z = expf(-fabsf(x));
    return (x >= 0.f) ? 1.f / (1.f + z) : z / (1.f + z);
}
__device__ __forceinline__ float clamp01(float v) { return fminf(fmaxf(v, 0.f), 1.f); }

// ---------------- 0: zero scratch that accumulates ----------------
__global__ void k_zero() {
    int i = blockIdx.x * blockDim.x + threadIdx.x;
    if (i < 3 * 65536) g_hist[i] = 0u;
    if (i < 3) g_candcnt[i] = 0;
    if (i < 48) g_validw[i] = 0ull;
}

// ---------------- 1: per-anchor max/argmax/sigmoid + histogram ----------------
__global__ void k_score(const float* __restrict__ c0, const float* __restrict__ c1,
                        const float* __restrict__ c2) {
    int warp = (blockIdx.x * blockDim.x + threadIdx.x) >> 5;
    int lane = threadIdx.x & 31;
    if (warp >= 86016) return;
    const float* cls;
    int l;
    int local;
    if (warp < 65536)      { l = 0; local = warp;          cls = c0; }
    else if (warp < 81920) { l = 1; local = warp - 65536;  cls = c1; }
    else                   { l = 2; local = warp - 81920;  cls = c2; }
    const float* row = cls + (size_t)local * 80;
    float v = row[lane];
    int ci = lane;
    float v1 = row[lane + 32];
    if (v1 > v) { v = v1; ci = lane + 32; }
    if (lane < 16) {
        float v2 = row[lane + 64];
        if (v2 > v) { v = v2; ci = lane + 64; }
    }
#pragma unroll
    for (int off = 16; off; off >>= 1) {
        float ov = __shfl_xor_sync(FULLMASK, v, off);
        int oc = __shfl_xor_sync(FULLMASK, ci, off);
        if (ov > v || (ov == v && oc < ci)) { v = ov; ci = oc; }
    }
    if (lane == 0) {
        float s = sigf(v);
        unsigned int u = __float_as_uint(s);
        u = (u & 0x80000000u) ? ~u : (u | 0x80000000u);
        g_u[warp] = u;
        g_label[warp] = (unsigned char)ci;
        atomicAdd(&g_hist[l * 65536 + (u >> 16)], 1u);
    }
}

// ---------------- 2: find boundary histogram bin (rank-1000 cut) ----------------
__global__ void k_boundary() {
    int l = blockIdx.x;
    int t = threadIdx.x;
    __shared__ unsigned int ch[1025];
    const unsigned int* H = g_hist + l * 65536;
    unsigned int sum = 0;
    for (int b = 0; b < 64; b++) sum += H[t * 64 + b];
    ch[t] = sum;
    if (t == 0) ch[1024] = 0;
    __syncthreads();
    for (int st = 1; st < 1024; st <<= 1) {   // suffix-sum (read, sync, write, sync)
        unsigned int v = (t + st < 1024) ? ch[t + st] : 0u;
        __syncthreads();
        ch[t] += v;
        __syncthreads();
    }
    unsigned int sufft = ch[t];
    unsigned int suffn = ch[t + 1];
    if (sufft >= 1000u && suffn < 1000u) {
        unsigned int cnt = suffn;
        for (int b = 63; b >= 0; b--) {
            unsigned int h = H[t * 64 + b];
            if (cnt + h >= 1000u) { g_B[l] = t * 64 + b; break; }
            cnt += h;
        }
    }
}

// ---------------- 3: gather candidates >= boundary bin ----------------
__global__ void k_gather() {
    int a = blockIdx.x * blockDim.x + threadIdx.x;
    if (a >= 86016) return;
    int l, base;
    if (a < 65536)      { l = 0; base = 0; }
    else if (a < 81920) { l = 1; base = 65536; }
    else                { l = 2; base = 81920; }
    unsigned int u = g_u[a];
    if ((int)(u >> 16) >= g_B[l]) {
        int p = atomicAdd(&g_candcnt[l], 1);
        if (p < 4096)
            g_cand[l * 4096 + p] =
                ((unsigned long long)u << 32) | (unsigned int)(0xFFFFFFFFu - (unsigned int)(a - base));
    }
}

// ---------------- 4: per-level bitonic top-1000 + decode + write outputs ----------------
__global__ void k_topk(const float* __restrict__ r0, const float* __restrict__ r1,
                       const float* __restrict__ r2, const float* __restrict__ scales,
                       float* __restrict__ out) {
    __shared__ unsigned long long s[4096];
    int l = blockIdx.x;
    int t = threadIdx.x;
    int K = g_candcnt[l];
    if (K > 4096) K = 4096;
    for (int i = t; i < 4096; i += 1024) s[i] = (i < K) ? g_cand[l * 4096 + i] : 0ull;
    __syncthreads();
    for (int k = 2; k <= 4096; k <<= 1)
        for (int j = k >> 1; j > 0; j >>= 1) {
            for (int i = t; i < 4096; i += 1024) {
                int ixj = i ^ j;
                if (ixj > i) {
                    unsigned long long a = s[i], b = s[ixj];
                    bool up = ((i & k) == 0);
                    if ((a > b) == up) { s[i] = b; s[ixj] = a; }
                }
            }
            __syncthreads();
        }
    if (t < 1000) {
        unsigned long long key = s[4095 - t];           // rank t (descending)
        unsigned int u = (unsigned int)(key >> 32);
        unsigned int local = 0xFFFFFFFFu - (unsigned int)key;
        unsigned int vb = (u & 0x80000000u) ? (u & 0x7FFFFFFFu) : ~u;
        float score = __uint_as_float(vb);
        int base = (l == 0) ? 0 : ((l == 1) ? 65536 : 81920);
        int logw = (l == 0) ? 8 : ((l == 1) ? 7 : 6);
        float stride = (l == 0) ? 8.f : ((l == 1) ? 16.f : 32.f);
        const float* rp = (l == 0) ? r0 : ((l == 1) ? r1 : r2);
        int lbl = g_label[base + local];
        int x = (int)(local & ((1u << logw) - 1u));
        int y = (int)(local >> logw);
        float ax = (x + 0.5f) * stride, ay = (y + 0.5f) * stride;
        float4 rg = ((const float4*)rp)[local];
        float cx = ax + (sigf(rg.x) * 3.0f - 1.5f);
        float cy = ay + (sigf(rg.y) * 3.0f - 1.5f);
        float sc = scales[l];
        float wv = expf(rg.z * sc), hv = expf(rg.w * sc);
        float x1 = (cx - 0.5f * wv) * stride, y1 = (cy - 0.5f * hv) * stride;
        float x2 = (cx + 0.5f * wv) * stride, y2 = (cy + 0.5f * hv) * stride;
        int o = l * 1000 + t;
        const float inv = 1.0f / 2048.0f;
        out[o * 4 + 0] = clamp01(x1 * inv);
        out[o * 4 + 1] = clamp01(y1 * inv);
        out[o * 4 + 2] = clamp01(x2 * inv);
        out[o * 4 + 3] = clamp01(y2 * inv);
        out[12000 + o] = score;
        out[15000 + o] = (float)lbl;
        float off = (float)lbl * 8192.0f;  // 4 * IMG_W
        g_nkey[o] = ((unsigned long long)u << 32) | (0xFFFFFFFFu - (unsigned int)o);
        g_nbox[o] = make_float4(x1 + off, y1 + off, x2 + off, y2 + off);
        g_nvalid[o] = (score >= 0.05f) ? 1 : 0;
    }
}

// ---------------- 5: global sort of 3000 dets by score (stable like argsort) ----------------
__global__ void k_nmssort() {
    __shared__ unsigned long long s[4096];
    int t = threadIdx.x;
    for (int i = t; i < 4096; i += 1024) s[i] = (i < 3000) ? g_nkey[i] : 0ull;
    __syncthreads();
    for (int k = 2; k <= 4096; k <<= 1)
        for (int j = k >> 1; j > 0; j >>= 1) {
            for (int i = t; i < 4096; i += 1024) {
                int ixj = i ^ j;
                if (ixj > i) {
                    unsigned long long a = s[i], b = s[ixj];
                    bool up = ((i & k) == 0);
                    if ((a > b) == up) { s[i] = b; s[ixj] = a; }
                }
            }
            __syncthreads();
        }
    for (int r = t; r < 3000; r += 1024) {
        unsigned long long key = s[4095 - r];
        int o = (int)(0xFFFFFFFFu - (unsigned int)key);
        g_sorder[r] = o;
        float4 b = g_nbox[o];
        g_sbox[r] = b;
        g_sarea[r] = (b.z - b.x) * (b.w - b.y);
        if (g_nvalid[o]) atomicOr(&g_validw[r >> 6], 1ull << (r & 63));
    }
}

// ---------------- 6: suppression bitmask matrix (3000 x 47 u64) ----------------
__global__ void k_iou() {
    int cb = blockIdx.x, rb = blockIdx.y;
    __shared__ float4 cbx[64];
    __shared__ float car[64];
    int t = threadIdx.x;
    int j0 = cb * 64;
    int j = j0 + t;
    if (j < 3000) { cbx[t] = g_sbox[j]; car[t] = g_sarea[j]; }
    else          { cbx[t] = make_float4(1e30f, 1e30f, 1e30f, 1e30f); car[t] = 0.f; }
    __syncthreads();
    int i = rb * 64 + t;
    if (i >= 3000) return;
    float4 bi = g_sbox[i];
    float ai = g_sarea[i];
    unsigned long long mask = 0ull;
    for (int jj = 0; jj < 64; jj++) {
        float4 bj = cbx[jj];
        float xx1 = fmaxf(bi.x, bj.x), yy1 = fmaxf(bi.y, bj.y);
        float xx2 = fminf(bi.z, bj.z), yy2 = fminf(bi.w, bj.w);
        float w = fmaxf(1e-10f, xx2 - xx1);
        float h = fmaxf(1e-10f, yy2 - yy1);
        float inter = w * h;
        float iou = inter / (ai + car[jj] - inter + 1e-14f);
        if (iou > 0.6f && (j0 + jj) > i) mask |= (1ull << jj);
    }
    g_supp[(size_t)i * 48 + cb] = mask;
}

// ---------------- 7: warp-serial greedy scan with register prefetch ----------------
__global__ void k_scan(float* __restrict__ out) {
    int l = threadIdx.x;  // 32 lanes; lane l owns words l and 32+l
    unsigned long long rem0 = ~g_validw[l];
    unsigned long long rem1 = (l < 15) ? ~g_validw[32 + l] : ~0ull;
    unsigned long long keep0 = 0ull, keep1 = 0ull;
    unsigned long long bufA[16], bufB[16];
#pragma unroll
    for (int d = 0; d < 16; d++) {
        bufA[d] = g_supp[(size_t)d * 48 + l];
        bufB[d] = (l < 15) ? g_supp[(size_t)d * 48 + 32 + l] : 0ull;
    }
    for (int base = 0; base < 3008; base += 16) {
#pragma unroll
        for (int d = 0; d < 16; d++) {
            int i = base + d;
            if (i < 3000) {
                int w = i >> 6, b = i & 63;
                int owner = w & 31;
                unsigned long long sel = (w < 32) ? rem0 : rem1;
                unsigned long long rw = __shfl_sync(FULLMASK, sel, owner);
                if (!((rw >> b) & 1ull)) {  // kept (valid & not suppressed)
                    rem0 |= bufA[d];
                    rem1 |= bufB[d];
                    if (l == owner) {
                        if (w < 32) keep0 |= 1ull << b;
                        else        keep1 |= 1ull << b;
                    }
                }
            }
            int pi = base + d + 16;
            if (pi < 3008) {
                bufA[d] = g_supp[(size_t)pi * 48 + l];
                bufB[d] = (l < 15) ? g_supp[(size_t)pi * 48 + 32 + l] : 0ull;
            }
        }
    }
    __shared__ unsigned long long kw[48];
    kw[l] = keep0;
    if (l < 15) kw[32 + l] = keep1;
    __syncwarp();
    for (int r = l; r < 3000; r += 32) {
        int kept = (int)((kw[r >> 6] >> (r & 63)) & 1ull);
        int o = g_sorder[r];
        out[18000 + o] = kept ? 1.0f : 0.0f;
    }
}

// ---------------- launch ----------------
extern "C" void kernel_launch(void* const* d_in, const int* in_sizes, int n_in,
                              void* d_out, int out_size) {
    (void)in_sizes; (void)n_in; (void)out_size;
    const float* c0 = (const float*)d_in[0];
    const float* r0 = (const float*)d_in[1];
    const float* c1 = (const float*)d_in[2];
    const float* r1 = (const float*)d_in[3];
    const float* c2 = (const float*)d_in[4];
    const float* r2 = (const float*)d_in[5];
    const float* sc = (const float*)d_in[6];
    float* out = (float*)d_out;

    k_zero<<<768, 256>>>();
    k_score<<<10752, 256>>>(c0, c1, c2);     // 8 warps/block, warp per anchor
    k_boundary<<<3, 1024>>>();
    k_gather<<<336, 256>>>();
    k_topk<<<3, 1024>>>(r0, r1, r2, sc, out);
    k_nmssort<<<1, 1024>>>();
    k_iou<<<dim3(47, 47), 64>>>();
    k_scan<<<1, 32>>>(out);
}

// round 2
// speedup vs baseline: 1.0206x; 1.0206x over previous
#include <cuda_runtime.h>

#define FULLMASK 0xffffffffu

// ---------------- scratch (static __device__, no allocations) ----------------
static __device__ unsigned int       g_u[86016];        // orderable score bits per anchor
static __device__ unsigned char      g_label[86016];    // argmax class per anchor
static __device__ unsigned int       g_hist[3 * 65536]; // 16-bit histograms per level
static __device__ int                g_B[3];            // boundary bin per level
static __device__ int                g_candcnt[3];
static __device__ unsigned long long g_cand[3 * 4096];  // (u<<32)|(~local_idx)
static __device__ unsigned long long g_nkey[3008];      // global NMS sort keys
static __device__ float4             g_nbox[3008];      // class-offset boxes (concat order)
static __device__ unsigned char      g_nvalid[3008];
static __device__ int                g_sorder[3008];    // sorted rank -> concat idx
static __device__ float4             g_sbox[3008];      // sorted boxes
static __device__ float              g_sarea[3008];
static __device__ unsigned long long g_validw[48];      // valid bits in sorted order
static __device__ unsigned long long g_supp[3008 * 48]; // suppression bit matrix

__device__ __forceinline__ float sigf(float x) {
    float z = expf(-fabsf(x));
    return (x >= 0.f) ? 1.f / (1.f + z) : z / (1.f + z);
}
__device__ __forceinline__ float clamp01(float v) { return fminf(fmaxf(v, 0.f), 1.f); }

// ---------------- 0: zero scratch that accumulates ----------------
__global__ void k_zero() {
    int i = blockIdx.x * blockDim.x + threadIdx.x;
    if (i < 3 * 65536) g_hist[i] = 0u;
    if (i < 3) g_candcnt[i] = 0;
    if (i < 48) g_validw[i] = 0ull;
}

// ---------------- 1: per-anchor max/argmax/sigmoid + histogram ----------------
__global__ void k_score(const float* __restrict__ c0, const float* __restrict__ c1,
                        const float* __restrict__ c2) {
    int warp = (blockIdx.x * blockDim.x + threadIdx.x) >> 5;
    int lane = threadIdx.x & 31;
    if (warp >= 86016) return;
    const float* cls;
    int l;
    int local;
    if (warp < 65536)      { l = 0; local = warp;          cls = c0; }
    else if (warp < 81920) { l = 1; local = warp - 65536;  cls = c1; }
    else                   { l = 2; local = warp - 81920;  cls = c2; }
    const float* row = cls + (size_t)local * 80;
    float v = row[lane];
    int ci = lane;
    float v1 = row[lane + 32];
    if (v1 > v) { v = v1; ci = lane + 32; }
    if (lane < 16) {
        float v2 = row[lane + 64];
        if (v2 > v) { v = v2; ci = lane + 64; }
    }
#pragma unroll
    for (int off = 16; off; off >>= 1) {
        float ov = __shfl_xor_sync(FULLMASK, v, off);
        int oc = __shfl_xor_sync(FULLMASK, ci, off);
        if (ov > v || (ov == v && oc < ci)) { v = ov; ci = oc; }
    }
    if (lane == 0) {
        float s = sigf(v);
        unsigned int u = __float_as_uint(s);
        u = (u & 0x80000000u) ? ~u : (u | 0x80000000u);
        g_u[warp] = u;
        g_label[warp] = (unsigned char)ci;
        atomicAdd(&g_hist[l * 65536 + (u >> 16)], 1u);
    }
}

// ---------------- 2: find boundary histogram bin (rank-1000 cut) ----------------
__global__ void k_boundary() {
    int l = blockIdx.x;
    int t = threadIdx.x;
    __shared__ unsigned int ch[1025];
    const unsigned int* H = g_hist + l * 65536;
    unsigned int sum = 0;
    for (int b = 0; b < 64; b++) sum += H[t * 64 + b];
    ch[t] = sum;
    if (t == 0) ch[1024] = 0;
    __syncthreads();
    for (int st = 1; st < 1024; st <<= 1) {   // suffix-sum (read, sync, write, sync)
        unsigned int v = (t + st < 1024) ? ch[t + st] : 0u;
        __syncthreads();
        ch[t] += v;
        __syncthreads();
    }
    unsigned int sufft = ch[t];
    unsigned int suffn = ch[t + 1];
    if (sufft >= 1000u && suffn < 1000u) {
        unsigned int cnt = suffn;
        for (int b = 63; b >= 0; b--) {
            unsigned int h = H[t * 64 + b];
            if (cnt + h >= 1000u) { g_B[l] = t * 64 + b; break; }
            cnt += h;
        }
    }
}

// ---------------- 3: gather candidates >= boundary bin ----------------
__global__ void k_gather() {
    int a = blockIdx.x * blockDim.x + threadIdx.x;
    if (a >= 86016) return;
    int l, base;
    if (a < 65536)      { l = 0; base = 0; }
    else if (a < 81920) { l = 1; base = 65536; }
    else                { l = 2; base = 81920; }
    unsigned int u = g_u[a];
    if ((int)(u >> 16) >= g_B[l]) {
        int p = atomicAdd(&g_candcnt[l], 1);
        if (p < 4096)
            g_cand[l * 4096 + p] =
                ((unsigned long long)u << 32) | (unsigned int)(0xFFFFFFFFu - (unsigned int)(a - base));
    }
}

// ---------------- 4: per-level bitonic top-1000 + decode + write outputs ----------------
__global__ void k_topk(const float* __restrict__ r0, const float* __restrict__ r1,
                       const float* __restrict__ r2, const float* __restrict__ scales,
                       float* __restrict__ out) {
    __shared__ unsigned long long s[4096];
    int l = blockIdx.x;
    int t = threadIdx.x;
    int K = g_candcnt[l];
    if (K > 4096) K = 4096;
    int n = (K <= 2048) ? 2048 : 4096;        // dynamic sort size (K is typically ~1.5k)
    for (int i = t; i < n; i += 1024) s[i] = (i < K) ? g_cand[l * 4096 + i] : 0ull;
    __syncthreads();
    for (int k = 2; k <= n; k <<= 1)
        for (int j = k >> 1; j > 0; j >>= 1) {
            for (int i = t; i < n; i += 1024) {
                int ixj = i ^ j;
                if (ixj > i) {
                    unsigned long long a = s[i], b = s[ixj];
                    bool up = ((i & k) == 0);
                    if ((a > b) == up) { s[i] = b; s[ixj] = a; }
                }
            }
            __syncthreads();
        }
    if (t < 1000) {
        unsigned long long key = s[n - 1 - t];          // rank t (descending)
        unsigned int u = (unsigned int)(key >> 32);
        unsigned int local = 0xFFFFFFFFu - (unsigned int)key;
        unsigned int vb = (u & 0x80000000u) ? (u & 0x7FFFFFFFu) : ~u;
        float score = __uint_as_float(vb);
        int base = (l == 0) ? 0 : ((l == 1) ? 65536 : 81920);
        int logw = (l == 0) ? 8 : ((l == 1) ? 7 : 6);
        float stride = (l == 0) ? 8.f : ((l == 1) ? 16.f : 32.f);
        const float* rp = (l == 0) ? r0 : ((l == 1) ? r1 : r2);
        int lbl = g_label[base + local];
        int x = (int)(local & ((1u << logw) - 1u));
        int y = (int)(local >> logw);
        float ax = (x + 0.5f) * stride, ay = (y + 0.5f) * stride;
        float4 rg = ((const float4*)rp)[local];
        float cx = ax + (sigf(rg.x) * 3.0f - 1.5f);
        float cy = ay + (sigf(rg.y) * 3.0f - 1.5f);
        float sc = scales[l];
        float wv = expf(rg.z * sc), hv = expf(rg.w * sc);
        float x1 = (cx - 0.5f * wv) * stride, y1 = (cy - 0.5f * hv) * stride;
        float x2 = (cx + 0.5f * wv) * stride, y2 = (cy + 0.5f * hv) * stride;
        int o = l * 1000 + t;
        const float inv = 1.0f / 2048.0f;
        out[o * 4 + 0] = clamp01(x1 * inv);
        out[o * 4 + 1] = clamp01(y1 * inv);
        out[o * 4 + 2] = clamp01(x2 * inv);
        out[o * 4 + 3] = clamp01(y2 * inv);
        out[12000 + o] = score;
        out[15000 + o] = (float)lbl;
        float off = (float)lbl * 8192.0f;  // 4 * IMG_W
        g_nkey[o] = ((unsigned long long)u << 32) | (0xFFFFFFFFu - (unsigned int)o);
        g_nbox[o] = make_float4(x1 + off, y1 + off, x2 + off, y2 + off);
        g_nvalid[o] = (score >= 0.05f) ? 1 : 0;
    }
}

// ---------------- 5: global sort of 3000 dets by score (stable like argsort) ----------------
__global__ void k_nmssort() {
    __shared__ unsigned long long s[4096];
    int t = threadIdx.x;
    for (int i = t; i < 4096; i += 1024) s[i] = (i < 3000) ? g_nkey[i] : 0ull;
    __syncthreads();
    for (int k = 2; k <= 4096; k <<= 1)
        for (int j = k >> 1; j > 0; j >>= 1) {
            for (int i = t; i < 4096; i += 1024) {
                int ixj = i ^ j;
                if (ixj > i) {
                    unsigned long long a = s[i], b = s[ixj];
                    bool up = ((i & k) == 0);
                    if ((a > b) == up) { s[i] = b; s[ixj] = a; }
                }
            }
            __syncthreads();
        }
    for (int r = t; r < 3000; r += 1024) {
        unsigned long long key = s[4095 - r];
        int o = (int)(0xFFFFFFFFu - (unsigned int)key);
        g_sorder[r] = o;
        float4 b = g_nbox[o];
        g_sbox[r] = b;
        g_sarea[r] = (b.z - b.x) * (b.w - b.y);
        if (g_nvalid[o]) atomicOr(&g_validw[r >> 6], 1ull << (r & 63));
    }
}

// ---------------- 6: suppression bitmask matrix (3000 x 47 u64), division-free ----------------
// iou > T  <=>  inter > T * (area_i + area_j - inter + 1e-14)   (union always > 0)
// Lower-triangle column blocks (all j < i) carry only bits the serial scan never
// re-reads -> write 0 and exit. Off-diagonal upper blocks need no per-pair j>i check.
__global__ void k_iou() {
    int cb = blockIdx.x;                       // column block 0..46
    __shared__ float4 cbx[64];
    __shared__ float car[64];
    int t = threadIdx.x;
    if (t < 64) {
        int j = cb * 64 + t;
        if (j < 3000) { cbx[t] = g_sbox[j]; car[t] = g_sarea[j]; }
        else          { cbx[t] = make_float4(1e30f, 1e30f, 1e30f, 1e30f); car[t] = 0.f; }
    }
    __syncthreads();
    int i = blockIdx.y * 256 + t;              // row 0..3071
    if (i >= 3000) return;
    if ((cb + 1) * 64 <= i) {                  // whole block has j < i
        g_supp[(size_t)i * 48 + cb] = 0ull;
        return;
    }
    float4 bi = g_sbox[i];
    float s = g_sarea[i] + 1e-14f;
    unsigned long long mask = 0ull;
    if (cb * 64 > i) {                         // whole block has j > i: no check
#pragma unroll 4
        for (int jj = 0; jj < 64; jj++) {
            float4 bj = cbx[jj];
            float xx1 = fmaxf(bi.x, bj.x), yy1 = fmaxf(bi.y, bj.y);
            float xx2 = fminf(bi.z, bj.z), yy2 = fminf(bi.w, bj.w);
            float w = fmaxf(1e-10f, xx2 - xx1);
            float h = fmaxf(1e-10f, yy2 - yy1);
            float inter = w * h;
            float u = (s + car[jj]) - inter;
            if (inter > 0.6f * u) mask |= (1ull << jj);
        }
    } else {                                   // diagonal block: need j > i
#pragma unroll 4
        for (int jj = 0; jj < 64; jj++) {
            float4 bj = cbx[jj];
            float xx1 = fmaxf(bi.x, bj.x), yy1 = fmaxf(bi.y, bj.y);
            float xx2 = fminf(bi.z, bj.z), yy2 = fminf(bi.w, bj.w);
            float w = fmaxf(1e-10f, xx2 - xx1);
            float h = fmaxf(1e-10f, yy2 - yy1);
            float inter = w * h;
            float u = (s + car[jj]) - inter;
            if (inter > 0.6f * u && (cb * 64 + jj) > i) mask |= (1ull << jj);
        }
    }
    g_supp[(size_t)i * 48 + cb] = mask;
}

// ---------------- 7: warp-serial greedy scan with register prefetch ----------------
__global__ void k_scan(float* __restrict__ out) {
    int l = threadIdx.x;  // 32 lanes; lane l owns words l and 32+l
    unsigned long long rem0 = ~g_validw[l];
    unsigned long long rem1 = (l < 15) ? ~g_validw[32 + l] : ~0ull;
    unsigned long long keep0 = 0ull, keep1 = 0ull;
    unsigned long long bufA[16], bufB[16];
#pragma unroll
    for (int d = 0; d < 16; d++) {
        bufA[d] = g_supp[(size_t)d * 48 + l];
        bufB[d] = (l < 15) ? g_supp[(size_t)d * 48 + 32 + l] : 0ull;
    }
    for (int base = 0; base < 3008; base += 16) {
#pragma unroll
        for (int d = 0; d < 16; d++) {
            int i = base + d;
            if (i < 3000) {
                int w = i >> 6, b = i & 63;
                int owner = w & 31;
                unsigned long long sel = (w < 32) ? rem0 : rem1;
                unsigned long long rw = __shfl_sync(FULLMASK, sel, owner);
                if (!((rw >> b) & 1ull)) {  // kept (valid & not suppressed)
                    rem0 |= bufA[d];
                    rem1 |= bufB[d];
                    if (l == owner) {
                        if (w < 32) keep0 |= 1ull << b;
                        else        keep1 |= 1ull << b;
                    }
                }
            }
            int pi = base + d + 16;
            if (pi < 3008) {
                bufA[d] = g_supp[(size_t)pi * 48 + l];
                bufB[d] = (l < 15) ? g_supp[(size_t)pi * 48 + 32 + l] : 0ull;
            }
        }
    }
    __shared__ unsigned long long kw[48];
    kw[l] = keep0;
    if (l < 15) kw[32 + l] = keep1;
    __syncwarp();
    for (int r = l; r < 3000; r += 32) {
        int kept = (int)((kw[r >> 6] >> (r & 63)) & 1ull);
        int o = g_sorder[r];
        out[18000 + o] = kept ? 1.0f : 0.0f;
    }
}

// ---------------- launch ----------------
extern "C" void kernel_launch(void* const* d_in, const int* in_sizes, int n_in,
                              void* d_out, int out_size) {
    (void)in_sizes; (void)n_in; (void)out_size;
    const float* c0 = (const float*)d_in[0];
    const float* r0 = (const float*)d_in[1];
    const float* c1 = (const float*)d_in[2];
    const float* r1 = (const float*)d_in[3];
    const float* c2 = (const float*)d_in[4];
    const float* r2 = (const float*)d_in[5];
    const float* sc = (const float*)d_in[6];
    float* out = (float*)d_out;

    k_zero<<<768, 256>>>();
    k_score<<<10752, 256>>>(c0, c1, c2);     // 8 warps/block, warp per anchor
    k_boundary<<<3, 1024>>>();
    k_gather<<<336, 256>>>();
    k_topk<<<3, 1024>>>(r0, r1, r2, sc, out);
    k_nmssort<<<1, 1024>>>();
    k_iou<<<dim3(47, 12), 256>>>();
    k_scan<<<1, 32>>>(out);
}

// round 6
// speedup vs baseline: 1.0564x; 1.0351x over previous
#include <cuda_runtime.h>

#define FULLMASK 0xffffffffu
typedef unsigned long long u64;
typedef unsigned int u32;

// ---------------- scratch (static __device__, zero-initialized, no allocations) ----------------
static __device__ u32           g_u[86016];         // orderable score bits per anchor
static __device__ unsigned char g_label[86016];     // argmax class per anchor
static __device__ u32           g_hist[3 * 262144]; // 18-bit histograms; re-zeroed by k_gather
static __device__ int           g_B[3];             // boundary bin per level
static __device__ int           g_candcnt[3];       // reset by k_topk
static __device__ u64           g_cand[3 * 2048];   // (u<<32)|(~local_idx)
static __device__ u64           g_lkey[3 * 1024];   // per-level sorted global keys
static __device__ float4        g_nbox[3008];       // class-offset boxes (concat order)
static __device__ unsigned char g_nvalid[3008];
static __device__ int           g_sorder[3008];     // sorted rank -> concat idx
static __device__ float4        g_sbox[3008];       // rank-ordered boxes
static __device__ float         g_sarea[3008];
static __device__ u64           g_validw[48];       // reset by k_scan
static __device__ u64           g_supp[3008 * 48];  // suppression bit matrix (rows >=3000 stay 0)

__device__ __forceinline__ float sigf(float x) {
    float z = expf(-fabsf(x));
    return (x >= 0.f) ? 1.f / (1.f + z) : z / (1.f + z);
}
__device__ __forceinline__ float clamp01(float v) { return fminf(fmaxf(v, 0.f), 1.f); }

// ---------------- 1: per-anchor max/argmax/sigmoid + 18-bit histogram ----------------
__global__ void __launch_bounds__(256) k_score(const float* __restrict__ c0,
                                               const float* __restrict__ c1,
                                               const float* __restrict__ c2) {
    int warp = (blockIdx.x * blockDim.x + threadIdx.x) >> 5;
    int lane = threadIdx.x & 31;
    if (warp >= 86016) return;
    const float* cls;
    int l, local;
    if (warp < 65536)      { l = 0; local = warp;          cls = c0; }
    else if (warp < 81920) { l = 1; local = warp - 65536;  cls = c1; }
    else                   { l = 2; local = warp - 81920;  cls = c2; }
    const float* row = cls + (size_t)local * 80;
    float v = row[lane];
    int ci = lane;
    float v1 = row[lane + 32];
    if (v1 > v) { v = v1; ci = lane + 32; }
    if (lane < 16) {
        float v2 = row[lane + 64];
        if (v2 > v) { v = v2; ci = lane + 64; }
    }
#pragma unroll
    for (int off = 16; off; off >>= 1) {
        float ov = __shfl_xor_sync(FULLMASK, v, off);
        int oc = __shfl_xor_sync(FULLMASK, ci, off);
        if (ov > v || (ov == v && oc < ci)) { v = ov; ci = oc; }
    }
    if (lane == 0) {
        float s = sigf(v);
        u32 u = __float_as_uint(s);
        u = (u & 0x80000000u) ? ~u : (u | 0x80000000u);
        g_u[warp] = u;
        g_label[warp] = (unsigned char)ci;
        atomicAdd(&g_hist[l * 262144 + (u >> 14)], 1u);
    }
}

// ---------------- 2: rank-1000 boundary bin, coalesced two-level ----------------
__global__ void __launch_bounds__(1024) k_boundary() {
    int l = blockIdx.x;
    int t = threadIdx.x;
    __shared__ u32 coarse[4096];   // 4096 coarse bins of 64 fine bins
    __shared__ u32 ts[1025];
    const u32* H = g_hist + l * 262144;
    for (int i = t; i < 4096; i += 1024) coarse[i] = 0;
    __syncthreads();
    int lane = t & 31, w = t >> 5;
    for (int p = 0; p < 256; p++) {
        u32 v = H[p * 1024 + t];                 // coalesced
#pragma unroll
        for (int off = 16; off; off >>= 1) v += __shfl_xor_sync(FULLMASK, v, off);
        if (lane == 0) atomicAdd(&coarse[p * 16 + (w >> 1)], v);
    }
    __syncthreads();
    u32 s4 = coarse[4 * t] + coarse[4 * t + 1] + coarse[4 * t + 2] + coarse[4 * t + 3];
    ts[t] = s4;
    if (t == 0) ts[1024] = 0;
    __syncthreads();
    for (int st = 1; st < 1024; st <<= 1) {      // suffix-sum
        u32 v = (t + st < 1024) ? ts[t + st] : 0u;
        __syncthreads();
        ts[t] += v;
        __syncthreads();
    }
    u32 sufft = ts[t], suffn = ts[t + 1];
    if (sufft >= 1000u && suffn < 1000u) {
        u32 cnt = suffn;
        int cse = -1;
#pragma unroll
        for (int c = 3; c >= 0; c--) {
            u32 h = coarse[4 * t + c];
            if (cse < 0) { if (cnt + h >= 1000u) cse = 4 * t + c; else cnt += h; }
        }
        const u32* HF = H + cse * 64;
        int B = 0;
        for (int base = 56; base >= 0; base -= 8) {   // 8-register rolling window
            u32 hh[8];
#pragma unroll
            for (int b = 0; b < 8; b++) hh[b] = HF[base + b];
#pragma unroll
            for (int b = 7; b >= 0; b--) {
                u32 h = hh[b];
                if (B == 0) { if (cnt + h >= 1000u) B = cse * 64 + base + b; else cnt += h; }
            }
            if (B) break;
        }
        g_B[l] = B;
    }
}

// ---------------- 3: gather candidates >= boundary bin; re-zero hist ----------------
__global__ void __launch_bounds__(256) k_gather() {
    int a = blockIdx.x * blockDim.x + threadIdx.x;   // grid = exactly 86016 threads
    for (int i = a; i < 3 * 262144; i += 86016) g_hist[i] = 0u;   // clean for next replay
    int l, base;
    if (a < 65536)      { l = 0; base = 0; }
    else if (a < 81920) { l = 1; base = 65536; }
    else                { l = 2; base = 81920; }
    u32 u = g_u[a];
    if ((int)(u >> 14) >= g_B[l]) {
        int p = atomicAdd(&g_candcnt[l], 1);
        if (p < 2048)
            g_cand[l * 2048 + p] =
                ((u64)u << 32) | (u32)(0xFFFFFFFFu - (u32)(a - base));
    }
}

// ---------------- 4: per-level 2048-key bitonic top-1000 + decode + outputs ----------------
__global__ void __launch_bounds__(1024) k_topk(const float* __restrict__ r0,
                                               const float* __restrict__ r1,
                                               const float* __restrict__ r2,
                                               const float* __restrict__ scales,
                                               float* __restrict__ out) {
    __shared__ u64 s[2048];
    int l = blockIdx.x;
    int t = threadIdx.x;
    int K = g_candcnt[l];
    if (K > 2048) K = 2048;
    s[t]        = (t < K)        ? g_cand[l * 2048 + t]        : 0ull;
    s[t + 1024] = (t + 1024 < K) ? g_cand[l * 2048 + t + 1024] : 0ull;
    __syncthreads();
    if (t == 0) g_candcnt[l] = 0;     // clean for next replay (after everyone read K)
    for (int k = 2; k <= 2048; k <<= 1)
        for (int j = k >> 1; j > 0; j >>= 1) {
#pragma unroll
            for (int it = 0; it < 2; it++) {
                int i = t + it * 1024;
                int ixj = i ^ j;
                if (ixj > i) {
                    u64 a = s[i], b = s[ixj];
                    bool up = ((i & k) == 0);
                    if ((a > b) == up) { s[i] = b; s[ixj] = a; }
                }
            }
            __syncthreads();
        }
    if (t < 1000) {
        u64 key = s[2047 - t];                   // rank t (descending)
        u32 u = (u32)(key >> 32);
        u32 local = 0xFFFFFFFFu - (u32)key;
        u32 vb = (u & 0x80000000u) ? (u & 0x7FFFFFFFu) : ~u;
        float score = __uint_as_float(vb);
        int base = (l == 0) ? 0 : ((l == 1) ? 65536 : 81920);
        int logw = (l == 0) ? 8 : ((l == 1) ? 7 : 6);
        float stride = (l == 0) ? 8.f : ((l == 1) ? 16.f : 32.f);
        const float* rp = (l == 0) ? r0 : ((l == 1) ? r1 : r2);
        int lbl = g_label[base + local];
        int x = (int)(local & ((1u << logw) - 1u));
        int y = (int)(local >> logw);
        float ax = (x + 0.5f) * stride, ay = (y + 0.5f) * stride;
        float4 rg = ((const float4*)rp)[local];
        float cx = ax + (sigf(rg.x) * 3.0f - 1.5f);
        float cy = ay + (sigf(rg.y) * 3.0f - 1.5f);
        float sc = scales[l];
        float wv = expf(rg.z * sc), hv = expf(rg.w * sc);
        float x1 = (cx - 0.5f * wv) * stride, y1 = (cy - 0.5f * hv) * stride;
        float x2 = (cx + 0.5f * wv) * stride, y2 = (cy + 0.5f * hv) * stride;
        int o = l * 1000 + t;
        const float inv = 1.0f / 2048.0f;
        out[o * 4 + 0] = clamp01(x1 * inv);
        out[o * 4 + 1] = clamp01(y1 * inv);
        out[o * 4 + 2] = clamp01(x2 * inv);
        out[o * 4 + 3] = clamp01(y2 * inv);
        out[12000 + o] = score;
        out[15000 + o] = (float)lbl;
        float off = (float)lbl * 8192.0f;        // 4 * IMG_W  (cross-class separation)
        g_lkey[l * 1024 + t] = ((u64)u << 32) | (0xFFFFFFFFu - (u32)o);  // tie-break: concat idx
        g_nbox[o] = make_float4(x1 + off, y1 + off, x2 + off, y2 + off);
        g_nvalid[o] = (score >= 0.05f) ? 1 : 0;
    }
}

// ---------------- 5: global rank via 3-way merge-by-rank (replaces bitonic sort) ----------------
__global__ void __launch_bounds__(1024) k_merge() {
    int l = blockIdx.x;
    int t = threadIdx.x;
    if (t >= 1000) return;
    u64 kg = g_lkey[l * 1024 + t];
    int r = t;                                    // elements above me in my own list
#pragma unroll
    for (int m = 0; m < 3; m++) {
        if (m == l) continue;
        const u64* arr = g_lkey + m * 1024;
        int lo = 0, hi = 1000;
        while (lo < hi) {                         // count of arr[] > kg (descending, distinct)
            int mid = (lo + hi) >> 1;
            if (arr[mid] > kg) lo = mid + 1; else hi = mid;
        }
        r += lo;
    }
    int o = l * 1000 + t;
    g_sorder[r] = o;
    float4 b = g_nbox[o];
    g_sbox[r] = b;
    g_sarea[r] = (b.z - b.x) * (b.w - b.y);
    if (g_nvalid[o]) atomicOr(&g_validw[r >> 6], 1ull << (r & 63));
}

// ---------------- 6: suppression bitmask matrix (division-free, upper-triangle only) ----------------
__global__ void __launch_bounds__(256) k_iou() {
    int cb = blockIdx.x;                       // column block 0..46
    __shared__ float4 cbx[64];
    __shared__ float car[64];
    int t = threadIdx.x;
    if (t < 64) {
        int j = cb * 64 + t;
        if (j < 3000) { cbx[t] = g_sbox[j]; car[t] = g_sarea[j]; }
        else          { cbx[t] = make_float4(1e30f, 1e30f, 1e30f, 1e30f); car[t] = 0.f; }
    }
    __syncthreads();
    int i = blockIdx.y * 256 + t;              // row
    if (i >= 3000) return;
    if ((cb + 1) * 64 <= i) {                  // whole block j < i: scan never reads these
        g_supp[(size_t)i * 48 + cb] = 0ull;
        return;
    }
    float4 bi = g_sbox[i];
    float s = g_sarea[i] + 1e-14f;
    u64 mask = 0ull;
    if (cb * 64 > i) {                         // strictly-above block: no per-pair check
#pragma unroll 4
        for (int jj = 0; jj < 64; jj++) {
            float4 bj = cbx[jj];
            float xx1 = fmaxf(bi.x, bj.x), yy1 = fmaxf(bi.y, bj.y);
            float xx2 = fminf(bi.z, bj.z), yy2 = fminf(bi.w, bj.w);
            float w = fmaxf(1e-10f, xx2 - xx1);
            float h = fmaxf(1e-10f, yy2 - yy1);
            float inter = w * h;
            float u = (s + car[jj]) - inter;
            if (inter > 0.6f * u) mask |= (1ull << jj);
        }
    } else {                                   // diagonal block: need j > i
#pragma unroll 4
        for (int jj = 0; jj < 64; jj++) {
            float4 bj = cbx[jj];
            float xx1 = fmaxf(bi.x, bj.x), yy1 = fmaxf(bi.y, bj.y);
            float xx2 = fminf(bi.z, bj.z), yy2 = fminf(bi.w, bj.w);
            float w = fmaxf(1e-10f, xx2 - xx1);
            float h = fmaxf(1e-10f, yy2 - yy1);
            float inter = w * h;
            float u = (s + car[jj]) - inter;
            if (inter > 0.6f * u && (cb * 64 + jj) > i) mask |= (1ull << jj);
        }
    }
    g_supp[(size_t)i * 48 + cb] = mask;
}

// ---------------- 7: word-parallel greedy scan (47 serial word-steps) ----------------
__global__ void __launch_bounds__(32) k_scan(float* __restrict__ out) {
    int l = threadIdx.x;  // 32 lanes; lane l owns removed-words l and 32+l
    u64 rem0 = ~g_validw[l];
    u64 rem1 = (l < 15) ? ~g_validw[32 + l] : ~0ull;
    __shared__ u64 kw[47];
    // prefetch diagonal rows for word 0: lane l holds dets 2l, 2l+1 of the word
    u64 d0 = g_supp[(size_t)(2 * l) * 48];
    u64 d1 = g_supp[(size_t)(2 * l + 1) * 48];
    for (int w = 0; w < 47; w++) {
        int owner = w & 31;
        u64 sel = (w < 32) ? rem0 : rem1;
        u64 rw = __shfl_sync(FULLMASK, sel, owner);   // removed-state of this word
        u64 my0 = d0, my1 = d1;
        if (w + 1 < 47) {                              // prefetch next word's diagonals
            int ibase = (w + 1) * 64 + 2 * l;
            d0 = g_supp[(size_t)ibase * 48 + (w + 1)];
            d1 = g_supp[(size_t)(ibase + 1) * 48 + (w + 1)];
        }
        u64 keepw = 0ull;
        // intra-word resolution: shfl sources loop-invariant -> off critical path
#pragma unroll
        for (int b = 0; b < 64; b++) {
            u64 row = __shfl_sync(FULLMASK, (b & 1) ? my1 : my0, b >> 1);
            u64 kept = ((rw >> b) & 1ull) ^ 1ull;
            rw |= kept ? row : 0ull;                   // row has only bits > b in word w
            keepw |= kept << b;
        }
        if (l == 0) kw[w] = keepw;
        // propagate kept rows into future removed words (rows have 0s for words < w)
        u64 kb = keepw;
        while (kb) {
            int b = __ffsll((long long)kb) - 1;
            kb &= kb - 1;
            size_t ri = (size_t)(w * 64 + b) * 48;
            rem0 |= g_supp[ri + l];
            if (l < 15) rem1 |= g_supp[ri + 32 + l];
        }
    }
    __syncwarp();
    g_validw[l] = 0ull;                                // clean for next replay
    if (l < 15) g_validw[32 + l] = 0ull;
    for (int r = l; r < 3000; r += 32) {
        int kept = (int)((kw[r >> 6] >> (r & 63)) & 1ull);
        out[18000 + g_sorder[r]] = kept ? 1.0f : 0.0f;
    }
}

// ---------------- launch ----------------
extern "C" void kernel_launch(void* const* d_in, const int* in_sizes, int n_in,
                              void* d_out, int out_size) {
    (void)in_sizes; (void)n_in; (void)out_size;
    const float* c0 = (const float*)d_in[0];
    const float* r0 = (const float*)d_in[1];
    const float* c1 = (const float*)d_in[2];
    const float* r1 = (const float*)d_in[3];
    const float* c2 = (const float*)d_in[4];
    const float* r2 = (const float*)d_in[5];
    const float* sc = (const float*)d_in[6];
    float* out = (float*)d_out;

    k_score<<<10752, 256>>>(c0, c1, c2);
    k_boundary<<<3, 1024>>>();
    k_gather<<<336, 256>>>();
    k_topk<<<3, 1024>>>(r0, r1, r2, sc, out);
    k_merge<<<3, 1024>>>();
    k_iou<<<dim3(47, 12), 256>>>();
    k_scan<<<1, 32>>>(out);
}

// round 7
// speedup vs baseline: 1.1374x; 1.0767x over previous
#include <cuda_runtime.h>

#define FULLMASK 0xffffffffu
#define NBLK 128
#define NTHR 1024
typedef unsigned long long u64;
typedef unsigned int u32;

// ---------------- scratch (static __device__, zero-initialized, no allocations) ----------------
static __device__ u32           g_u[86016];        // orderable score bits per anchor
static __device__ unsigned char g_label[86016];    // argmax class per anchor
static __device__ u32           g_h12[3 * 4096];   // 12-bit hist; zeroed in phase C
static __device__ u32           g_h8[3 * 256];     // 8-bit refine hist; zeroed in phase E
static __device__ int           g_B12[3];          // boundary 12-bit bin
static __device__ int           g_C12[3];          // count strictly above boundary bin
static __device__ int           g_T20[3];          // 20-bit threshold (u>>12 >= T20)
static __device__ int           g_candcnt[3];      // reset in phase F
static __device__ u64           g_cand[3 * 2048];
static __device__ u64           g_lkey[3 * 1024];  // per-level sorted global keys
static __device__ float4        g_nbox[3008];
static __device__ unsigned char g_nvalid[3008];
static __device__ int           g_sorder[3008];
static __device__ float4        g_sbox[3008];
static __device__ float         g_sarea[3008];
static __device__ u64           g_validw[48];      // reset in phase J
static __device__ u64           g_supp[3008 * 48]; // fully rewritten each run
static __device__ int           g_cnt;             // barrier count (returns to 0)
static __device__ volatile int  g_gen;             // barrier generation (monotonic)

__device__ __forceinline__ float sigf(float x) {
    float z = expf(-fabsf(x));
    return (x >= 0.f) ? 1.f / (1.f + z) : z / (1.f + z);
}
__device__ __forceinline__ float clamp01(float v) { return fminf(fmaxf(v, 0.f), 1.f); }

// software global barrier: all NBLK blocks are co-resident (grid <= SM count, 1 block/SM)
__device__ __forceinline__ void gbar() {
    __syncthreads();
    if (threadIdx.x == 0) {
        __threadfence();
        int gen = g_gen;
        if (atomicAdd(&g_cnt, 1) == NBLK - 1) {
            g_cnt = 0;
            __threadfence();
            g_gen = gen + 1;
        } else {
            while (g_gen == gen) { }
        }
        __threadfence();
    }
    __syncthreads();
}

__global__ void __launch_bounds__(NTHR, 1) k_all(
    const float* __restrict__ c0, const float* __restrict__ r0,
    const float* __restrict__ c1, const float* __restrict__ r1,
    const float* __restrict__ c2, const float* __restrict__ r2,
    const float* __restrict__ scales, float* __restrict__ out)
{
    __shared__ u32    sh[4096];
    __shared__ u32    ts[1025];
    __shared__ u64    skey[2048];
    __shared__ float4 s_cbx[64];
    __shared__ float  s_car[64];
    __shared__ u64    s_kw[47];

    const int bl = blockIdx.x;
    const int t  = threadIdx.x;
    const int gtid = bl * NTHR + t;
    const int lane = t & 31;

    // ---------- Phase A: score + per-block smem 12-bit histogram ----------
    {
        for (int i = t; i < 4096; i += NTHR) sh[i] = 0;
        __syncthreads();
        int l, abase, acount, bfirst, bnum;
        const float* cls;
        if (bl < 98)       { l = 0; abase = 0;     acount = 65536; bfirst = 0;   bnum = 98; cls = c0; }
        else if (bl < 117) { l = 1; abase = 65536; acount = 16384; bfirst = 98;  bnum = 19; cls = c1; }
        else               { l = 2; abase = 81920; acount = 4096;  bfirst = 117; bnum = 11; cls = c2; }
        int gw = (bl - bfirst) * 32 + (t >> 5);
        int step = bnum * 32;
        for (int li = gw; li < acount; li += step) {
            const float* row = cls + (size_t)li * 80;
            float v = row[lane];
            int ci = lane;
            float v1 = row[lane + 32];
            if (v1 > v) { v = v1; ci = lane + 32; }
            if (lane < 16) {
                float v2 = row[lane + 64];
                if (v2 > v) { v = v2; ci = lane + 64; }
            }
#pragma unroll
            for (int off = 16; off; off >>= 1) {
                float ov = __shfl_xor_sync(FULLMASK, v, off);
                int oc = __shfl_xor_sync(FULLMASK, ci, off);
                if (ov > v || (ov == v && oc < ci)) { v = ov; ci = oc; }
            }
            if (lane == 0) {
                float s = sigf(v);
                u32 u = __float_as_uint(s);
                u = (u & 0x80000000u) ? ~u : (u | 0x80000000u);
                g_u[abase + li] = u;
                g_label[abase + li] = (unsigned char)ci;
                atomicAdd(&sh[u >> 20], 1u);
            }
        }
        __syncthreads();
        for (int i = t; i < 4096; i += NTHR)
            if (sh[i]) atomicAdd(&g_h12[l * 4096 + i], sh[i]);
    }
    gbar();

    // ---------- Phase B: coarse boundary bin (blocks 0-2) ----------
    if (bl < 3) {
        for (int i = t; i < 4096; i += NTHR) sh[i] = g_h12[bl * 4096 + i];
        __syncthreads();
        u32 s4 = sh[4 * t] + sh[4 * t + 1] + sh[4 * t + 2] + sh[4 * t + 3];
        ts[t] = s4;
        if (t == 0) ts[1024] = 0;
        __syncthreads();
        for (int st = 1; st < 1024; st <<= 1) {
            u32 v = (t + st < 1024) ? ts[t + st] : 0u;
            __syncthreads();
            ts[t] += v;
            __syncthreads();
        }
        u32 sufft = ts[t], suffn = ts[t + 1];
        if (sufft >= 1000u && suffn < 1000u) {
            u32 cnt = suffn;
            int b12 = -1;
#pragma unroll
            for (int c = 3; c >= 0; c--) {
                u32 h = sh[4 * t + c];
                if (b12 < 0) { if (cnt + h >= 1000u) b12 = 4 * t + c; else cnt += h; }
            }
            g_B12[bl] = b12;
            g_C12[bl] = (int)cnt;         // strictly above boundary bin
        }
    }
    gbar();

    // ---------- Phase C: 8-bit refinement hist over boundary-bin anchors; zero h12 ----------
    {
        if (gtid < 12288) g_h12[gtid] = 0;
        if (gtid < 86016) {
            int l = (gtid < 65536) ? 0 : ((gtid < 81920) ? 1 : 2);
            u32 u = g_u[gtid];
            if ((int)(u >> 20) == g_B12[l])
                atomicAdd(&g_h8[l * 256 + ((u >> 12) & 255u)], 1u);
        }
    }
    gbar();

    // ---------- Phase D: refine to 20-bit threshold (blocks 0-2) ----------
    if (bl < 3) {
        if (t < 256) ts[t] = g_h8[bl * 256 + t];
        if (t == 0) ts[256] = 0;
        __syncthreads();
        for (int st = 1; st < 256; st <<= 1) {
            u32 v = (t < 256 && t + st < 256) ? ts[t + st] : 0u;
            __syncthreads();
            if (t < 256) ts[t] += v;
            __syncthreads();
        }
        if (t < 256) {
            int C = g_C12[bl];
            int sufft = (int)ts[t], suffn = (int)ts[t + 1];
            if (sufft + C >= 1000 && suffn + C < 1000)
                g_T20[bl] = (g_B12[bl] << 8) | t;
        }
    }
    gbar();

    // ---------- Phase E: gather candidates; zero h8 ----------
    {
        if (gtid < 768) g_h8[gtid] = 0;
        if (gtid < 86016) {
            int l, base;
            if (gtid < 65536)      { l = 0; base = 0; }
            else if (gtid < 81920) { l = 1; base = 65536; }
            else                   { l = 2; base = 81920; }
            u32 u = g_u[gtid];
            if ((int)(u >> 12) >= g_T20[l]) {
                int p = atomicAdd(&g_candcnt[l], 1);
                if (p < 2048)
                    g_cand[l * 2048 + p] =
                        ((u64)u << 32) | (u32)(0xFFFFFFFFu - (u32)(gtid - base));
            }
        }
    }
    gbar();

    // ---------- Phase F: per-level 2048-key bitonic top-1000 + decode + outputs (blocks 0-2) ----------
    if (bl < 3) {
        int l = bl;
        int K = g_candcnt[l];
        if (K > 2048) K = 2048;
        skey[t]        = (t < K)        ? g_cand[l * 2048 + t]        : 0ull;
        skey[t + 1024] = (t + 1024 < K) ? g_cand[l * 2048 + t + 1024] : 0ull;
        __syncthreads();
        if (t == 0) g_candcnt[l] = 0;        // clean for next replay
        for (int k = 2; k <= 2048; k <<= 1)
            for (int j = k >> 1; j > 0; j >>= 1) {
#pragma unroll
                for (int it = 0; it < 2; it++) {
                    int i = t + it * 1024;
                    int ixj = i ^ j;
                    if (ixj > i) {
                        u64 a = skey[i], b = skey[ixj];
                        bool up = ((i & k) == 0);
                        if ((a > b) == up) { skey[i] = b; skey[ixj] = a; }
                    }
                }
                __syncthreads();
            }
        if (t < 1000) {
            u64 key = skey[2047 - t];
            u32 u = (u32)(key >> 32);
            u32 local = 0xFFFFFFFFu - (u32)key;
            u32 vb = (u & 0x80000000u) ? (u & 0x7FFFFFFFu) : ~u;
            float score = __uint_as_float(vb);
            int base = (l == 0) ? 0 : ((l == 1) ? 65536 : 81920);
            int logw = (l == 0) ? 8 : ((l == 1) ? 7 : 6);
            float stride = (l == 0) ? 8.f : ((l == 1) ? 16.f : 32.f);
            const float* rp = (l == 0) ? r0 : ((l == 1) ? r1 : r2);
            int lbl = g_label[base + local];
            int x = (int)(local & ((1u << logw) - 1u));
            int y = (int)(local >> logw);
            float ax = (x + 0.5f) * stride, ay = (y + 0.5f) * stride;
            float4 rg = ((const float4*)rp)[local];
            float cx = ax + (sigf(rg.x) * 3.0f - 1.5f);
            float cy = ay + (sigf(rg.y) * 3.0f - 1.5f);
            float sc = scales[l];
            float wv = expf(rg.z * sc), hv = expf(rg.w * sc);
            float x1 = (cx - 0.5f * wv) * stride, y1 = (cy - 0.5f * hv) * stride;
            float x2 = (cx + 0.5f * wv) * stride, y2 = (cy + 0.5f * hv) * stride;
            int o = l * 1000 + t;
            const float inv = 1.0f / 2048.0f;
            out[o * 4 + 0] = clamp01(x1 * inv);
            out[o * 4 + 1] = clamp01(y1 * inv);
            out[o * 4 + 2] = clamp01(x2 * inv);
            out[o * 4 + 3] = clamp01(y2 * inv);
            out[12000 + o] = score;
            out[15000 + o] = (float)lbl;
            float off = (float)lbl * 8192.0f;    // 4 * IMG_W (cross-class separation)
            g_lkey[l * 1024 + t] = ((u64)u << 32) | (0xFFFFFFFFu - (u32)o);
            g_nbox[o] = make_float4(x1 + off, y1 + off, x2 + off, y2 + off);
            g_nvalid[o] = (score >= 0.05f) ? 1 : 0;
        }
    }
    gbar();

    // ---------- Phase G: 3-way merge-by-rank (blocks 0-2) ----------
    if (bl < 3 && t < 1000) {
        int l = bl;
        u64 kg = g_lkey[l * 1024 + t];
        int r = t;
#pragma unroll
        for (int m = 0; m < 3; m++) {
            if (m == l) continue;
            const u64* arr = g_lkey + m * 1024;
            int lo = 0, hi = 1000;
            while (lo < hi) {
                int mid = (lo + hi) >> 1;
                if (arr[mid] > kg) lo = mid + 1; else hi = mid;
            }
            r += lo;
        }
        int o = l * 1000 + t;
        g_sorder[r] = o;
        float4 b = g_nbox[o];
        g_sbox[r] = b;
        g_sarea[r] = (b.z - b.x) * (b.w - b.y);
        if (g_nvalid[o]) atomicOr(&g_validw[r >> 6], 1ull << (r & 63));
    }
    gbar();

    // ---------- Phase H: suppression bitmask matrix (141 tiles over 128 blocks) ----------
    for (int tile = bl; tile < 141; tile += NBLK) {
        int cb = tile % 47, ch = tile / 47;
        __syncthreads();
        if (t < 64) {
            int j = cb * 64 + t;
            if (j < 3000) { s_cbx[t] = g_sbox[j]; s_car[t] = g_sarea[j]; }
            else          { s_cbx[t] = make_float4(1e30f, 1e30f, 1e30f, 1e30f); s_car[t] = 0.f; }
        }
        __syncthreads();
        int i = ch * 1024 + t;
        if (i < 3000) {
            if ((cb + 1) * 64 <= i) {
                g_supp[(size_t)i * 48 + cb] = 0ull;
            } else {
                float4 bi = g_sbox[i];
                float s = g_sarea[i] + 1e-14f;
                u64 mask = 0ull;
                if (cb * 64 > i) {
#pragma unroll 4
                    for (int jj = 0; jj < 64; jj++) {
                        float4 bj = s_cbx[jj];
                        float xx1 = fmaxf(bi.x, bj.x), yy1 = fmaxf(bi.y, bj.y);
                        float xx2 = fminf(bi.z, bj.z), yy2 = fminf(bi.w, bj.w);
                        float w = fmaxf(1e-10f, xx2 - xx1);
                        float h = fmaxf(1e-10f, yy2 - yy1);
                        float inter = w * h;
                        float u = (s + s_car[jj]) - inter;
                        if (inter > 0.6f * u) mask |= (1ull << jj);
                    }
                } else {
#pragma unroll 4
                    for (int jj = 0; jj < 64; jj++) {
                        float4 bj = s_cbx[jj];
                        float xx1 = fmaxf(bi.x, bj.x), yy1 = fmaxf(bi.y, bj.y);
                        float xx2 = fminf(bi.z, bj.z), yy2 = fminf(bi.w, bj.w);
                        float w = fmaxf(1e-10f, xx2 - xx1);
                        float h = fmaxf(1e-10f, yy2 - yy1);
                        float inter = w * h;
                        float u = (s + s_car[jj]) - inter;
                        if (inter > 0.6f * u && (cb * 64 + jj) > i) mask |= (1ull << jj);
                    }
                }
                g_supp[(size_t)i * 48 + cb] = mask;
            }
        }
    }
    gbar();

    // ---------- Phase I+J: word-parallel greedy scan + keep outputs (block 0 only) ----------
    if (bl != 0) return;
    if (t < 32) {
        int l = t;
        u64 rem0 = ~g_validw[l];
        u64 rem1 = (l < 15) ? ~g_validw[32 + l] : ~0ull;
        u64 d0 = g_supp[(size_t)(2 * l) * 48];
        u64 d1 = g_supp[(size_t)(2 * l + 1) * 48];
        for (int w = 0; w < 47; w++) {
            int owner = w & 31;
            u64 sel = (w < 32) ? rem0 : rem1;
            u64 rw = __shfl_sync(FULLMASK, sel, owner);
            u64 my0 = d0, my1 = d1;
            if (w + 1 < 47) {
                int ibase = (w + 1) * 64 + 2 * l;
                d0 = g_supp[(size_t)ibase * 48 + (w + 1)];
                d1 = g_supp[(size_t)(ibase + 1) * 48 + (w + 1)];
            }
            u64 keepw = 0ull;
#pragma unroll
            for (int b = 0; b < 64; b++) {
                u64 row = __shfl_sync(FULLMASK, (b & 1) ? my1 : my0, b >> 1);
                u64 kept = ((rw >> b) & 1ull) ^ 1ull;
                rw |= kept ? row : 0ull;
                keepw |= kept << b;
            }
            if (l == 0) s_kw[w] = keepw;
            u64 kb = keepw;
            while (kb) {
                int b = __ffsll((long long)kb) - 1;
                kb &= kb - 1;
                size_t ri = (size_t)(w * 64 + b) * 48;
                rem0 |= g_supp[ri + l];
                if (l < 15) rem1 |= g_supp[ri + 32 + l];
            }
        }
    }
    __syncthreads();
    if (t < 48) g_validw[t] = 0ull;                    // clean for next replay
    for (int r = t; r < 3000; r += NTHR) {
        int kept = (int)((s_kw[r >> 6] >> (r & 63)) & 1ull);
        out[18000 + g_sorder[r]] = kept ? 1.0f : 0.0f;
    }
}

// ---------------- launch ----------------
extern "C" void kernel_launch(void* const* d_in, const int* in_sizes, int n_in,
                              void* d_out, int out_size) {
    (void)in_sizes; (void)n_in; (void)out_size;
    const float* c0 = (const float*)d_in[0];
    const float* r0 = (const float*)d_in[1];
    const float* c1 = (const float*)d_in[2];
    const float* r1 = (const float*)d_in[3];
    const float* c2 = (const float*)d_in[4];
    const float* r2 = (const float*)d_in[5];
    const float* sc = (const float*)d_in[6];
    float* out = (float*)d_out;

    k_all<<<NBLK, NTHR>>>(c0, r0, c1, r1, c2, r2, sc, out);
}

// round 8
// speedup vs baseline: 6.7984x; 5.9770x over previous
#include <cuda_runtime.h>

#define FULLMASK 0xffffffffu
#define NBLK 128
#define NTHR 1024
typedef unsigned long long u64;
typedef unsigned int u32;

// ---------------- scratch (static __device__, zero-initialized, no allocations) ----------------
static __device__ u32           g_u[86016];        // orderable score bits per anchor
static __device__ unsigned char g_label[86016];    // argmax class per anchor
static __device__ u32           g_h12[3 * 4096];   // 12-bit hist; zeroed in phase C
static __device__ u32           g_h8[3 * 256];     // 8-bit refine hist; zeroed in phase E
static __device__ int           g_B12[3];          // boundary 12-bit bin
static __device__ int           g_C12[3];          // count strictly above boundary bin
static __device__ int           g_T20[3];          // 20-bit threshold (u>>12 >= T20)
static __device__ int           g_candcnt[3];      // reset in phase F
static __device__ u64           g_cand[3 * 2048];
static __device__ u64           g_lkey[3 * 1024];  // per-level sorted global keys
static __device__ float4        g_nbox[3008];
static __device__ unsigned char g_nvalid[3008];
static __device__ int           g_sorder[3008];
static __device__ float4        g_sbox[3008];
static __device__ float         g_sarea[3008];
static __device__ u64           g_validw[48];      // reset in phase J
static __device__ u64           g_supp[3008 * 48]; // rows >= 3000 stay 0 forever
static __device__ int           g_cnt;             // barrier count (returns to 0)
static __device__ volatile int  g_gen;             // barrier generation (monotonic)

__device__ __forceinline__ float sigf(float x) {
    float z = expf(-fabsf(x));
    return (x >= 0.f) ? 1.f / (1.f + z) : z / (1.f + z);
}
__device__ __forceinline__ float clamp01(float v) { return fminf(fmaxf(v, 0.f), 1.f); }

// warp-wide OR butterfly reduce on u64: every lane ends with the full OR
__device__ __forceinline__ u64 warp_or(u64 v) {
#pragma unroll
    for (int off = 16; off; off >>= 1) {
        u32 lo = (u32)v, hi = (u32)(v >> 32);
        lo |= __shfl_xor_sync(FULLMASK, lo, off);
        hi |= __shfl_xor_sync(FULLMASK, hi, off);
        v = ((u64)hi << 32) | lo;
    }
    return v;
}

// software global barrier: all NBLK blocks co-resident (grid <= SM count)
__device__ __forceinline__ void gbar() {
    __syncthreads();
    if (threadIdx.x == 0) {
        __threadfence();
        int gen = g_gen;
        if (atomicAdd(&g_cnt, 1) == NBLK - 1) {
            g_cnt = 0;
            __threadfence();
            g_gen = gen + 1;
        } else {
            while (g_gen == gen) { }
        }
        __threadfence();
    }
    __syncthreads();
}

__global__ void __launch_bounds__(NTHR, 1) k_all(
    const float* __restrict__ c0, const float* __restrict__ r0,
    const float* __restrict__ c1, const float* __restrict__ r1,
    const float* __restrict__ c2, const float* __restrict__ r2,
    const float* __restrict__ scales, float* __restrict__ out)
{
    __shared__ u32    sh[4096];
    __shared__ u32    ts[1025];
    __shared__ u64    skey[2048];
    __shared__ float4 s_cbx[64];
    __shared__ float  s_car[64];
    __shared__ u64    s_kw[47];     // kept bits per word
    __shared__ u64    s_rem[48];    // removed/invalid bits per word
    __shared__ u64    s_diag[2][64];// double-buffered diagonal rows

    const int bl = blockIdx.x;
    const int t  = threadIdx.x;
    const int gtid = bl * NTHR + t;
    const int lane = t & 31;
    const int wid  = t >> 5;

    // ---------- Phase A: score + per-block smem 12-bit histogram ----------
    {
        for (int i = t; i < 4096; i += NTHR) sh[i] = 0;
        __syncthreads();
        int l, abase, acount, bfirst, bnum;
        const float* cls;
        if (bl < 98)       { l = 0; abase = 0;     acount = 65536; bfirst = 0;   bnum = 98; cls = c0; }
        else if (bl < 117) { l = 1; abase = 65536; acount = 16384; bfirst = 98;  bnum = 19; cls = c1; }
        else               { l = 2; abase = 81920; acount = 4096;  bfirst = 117; bnum = 11; cls = c2; }
        int gw = (bl - bfirst) * 32 + wid;
        int step = bnum * 32;
        for (int li = gw; li < acount; li += step) {
            const float* row = cls + (size_t)li * 80;
            float v = row[lane];
            int ci = lane;
            float v1 = row[lane + 32];
            if (v1 > v) { v = v1; ci = lane + 32; }
            if (lane < 16) {
                float v2 = row[lane + 64];
                if (v2 > v) { v = v2; ci = lane + 64; }
            }
#pragma unroll
            for (int off = 16; off; off >>= 1) {
                float ov = __shfl_xor_sync(FULLMASK, v, off);
                int oc = __shfl_xor_sync(FULLMASK, ci, off);
                if (ov > v || (ov == v && oc < ci)) { v = ov; ci = oc; }
            }
            if (lane == 0) {
                float s = sigf(v);
                u32 u = __float_as_uint(s);
                u = (u & 0x80000000u) ? ~u : (u | 0x80000000u);
                g_u[abase + li] = u;
                g_label[abase + li] = (unsigned char)ci;
                atomicAdd(&sh[u >> 20], 1u);
            }
        }
        __syncthreads();
        for (int i = t; i < 4096; i += NTHR)
            if (sh[i]) atomicAdd(&g_h12[l * 4096 + i], sh[i]);
    }
    gbar();

    // ---------- Phase B: coarse boundary bin (blocks 0-2) ----------
    if (bl < 3) {
        for (int i = t; i < 4096; i += NTHR) sh[i] = g_h12[bl * 4096 + i];
        __syncthreads();
        u32 s4 = sh[4 * t] + sh[4 * t + 1] + sh[4 * t + 2] + sh[4 * t + 3];
        ts[t] = s4;
        if (t == 0) ts[1024] = 0;
        __syncthreads();
        for (int st = 1; st < 1024; st <<= 1) {
            u32 v = (t + st < 1024) ? ts[t + st] : 0u;
            __syncthreads();
            ts[t] += v;
            __syncthreads();
        }
        u32 sufft = ts[t], suffn = ts[t + 1];
        if (sufft >= 1000u && suffn < 1000u) {
            u32 cnt = suffn;
            int b12 = -1;
#pragma unroll
            for (int c = 3; c >= 0; c--) {
                u32 h = sh[4 * t + c];
                if (b12 < 0) { if (cnt + h >= 1000u) b12 = 4 * t + c; else cnt += h; }
            }
            g_B12[bl] = b12;
            g_C12[bl] = (int)cnt;
        }
    }
    gbar();

    // ---------- Phase C: 8-bit refinement hist; zero h12 ----------
    {
        if (gtid < 12288) g_h12[gtid] = 0;
        if (gtid < 86016) {
            int l = (gtid < 65536) ? 0 : ((gtid < 81920) ? 1 : 2);
            u32 u = g_u[gtid];
            if ((int)(u >> 20) == g_B12[l])
                atomicAdd(&g_h8[l * 256 + ((u >> 12) & 255u)], 1u);
        }
    }
    gbar();

    // ---------- Phase D: refine to 20-bit threshold (blocks 0-2) ----------
    if (bl < 3) {
        if (t < 256) ts[t] = g_h8[bl * 256 + t];
        if (t == 0) ts[256] = 0;
        __syncthreads();
        for (int st = 1; st < 256; st <<= 1) {
            u32 v = (t < 256 && t + st < 256) ? ts[t + st] : 0u;
            __syncthreads();
            if (t < 256) ts[t] += v;
            __syncthreads();
        }
        if (t < 256) {
            int C = g_C12[bl];
            int sufft = (int)ts[t], suffn = (int)ts[t + 1];
            if (sufft + C >= 1000 && suffn + C < 1000)
                g_T20[bl] = (g_B12[bl] << 8) | t;
        }
    }
    gbar();

    // ---------- Phase E: gather candidates; zero h8 ----------
    {
        if (gtid < 768) g_h8[gtid] = 0;
        if (gtid < 86016) {
            int l, base;
            if (gtid < 65536)      { l = 0; base = 0; }
            else if (gtid < 81920) { l = 1; base = 65536; }
            else                   { l = 2; base = 81920; }
            u32 u = g_u[gtid];
            if ((int)(u >> 12) >= g_T20[l]) {
                int p = atomicAdd(&g_candcnt[l], 1);
                if (p < 2048)
                    g_cand[l * 2048 + p] =
                        ((u64)u << 32) | (u32)(0xFFFFFFFFu - (u32)(gtid - base));
            }
        }
    }
    gbar();

    // ---------- Phase F: per-level 2048-key bitonic top-1000 + decode + outputs (blocks 0-2) ----------
    if (bl < 3) {
        int l = bl;
        int K = g_candcnt[l];
        if (K > 2048) K = 2048;
        skey[t]        = (t < K)        ? g_cand[l * 2048 + t]        : 0ull;
        skey[t + 1024] = (t + 1024 < K) ? g_cand[l * 2048 + t + 1024] : 0ull;
        __syncthreads();
        if (t == 0) g_candcnt[l] = 0;
        for (int k = 2; k <= 2048; k <<= 1)
            for (int j = k >> 1; j > 0; j >>= 1) {
#pragma unroll
                for (int it = 0; it < 2; it++) {
                    int i = t + it * 1024;
                    int ixj = i ^ j;
                    if (ixj > i) {
                        u64 a = skey[i], b = skey[ixj];
                        bool up = ((i & k) == 0);
                        if ((a > b) == up) { skey[i] = b; skey[ixj] = a; }
                    }
                }
                __syncthreads();
            }
        if (t < 1000) {
            u64 key = skey[2047 - t];
            u32 u = (u32)(key >> 32);
            u32 local = 0xFFFFFFFFu - (u32)key;
            u32 vb = (u & 0x80000000u) ? (u & 0x7FFFFFFFu) : ~u;
            float score = __uint_as_float(vb);
            int base = (l == 0) ? 0 : ((l == 1) ? 65536 : 81920);
            int logw = (l == 0) ? 8 : ((l == 1) ? 7 : 6);
            float stride = (l == 0) ? 8.f : ((l == 1) ? 16.f : 32.f);
            const float* rp = (l == 0) ? r0 : ((l == 1) ? r1 : r2);
            int lbl = g_label[base + local];
            int x = (int)(local & ((1u << logw) - 1u));
            int y = (int)(local >> logw);
            float ax = (x + 0.5f) * stride, ay = (y + 0.5f) * stride;
            float4 rg = ((const float4*)rp)[local];
            float cx = ax + (sigf(rg.x) * 3.0f - 1.5f);
            float cy = ay + (sigf(rg.y) * 3.0f - 1.5f);
            float sc = scales[l];
            float wv = expf(rg.z * sc), hv = expf(rg.w * sc);
            float x1 = (cx - 0.5f * wv) * stride, y1 = (cy - 0.5f * hv) * stride;
            float x2 = (cx + 0.5f * wv) * stride, y2 = (cy + 0.5f * hv) * stride;
            int o = l * 1000 + t;
            const float inv = 1.0f / 2048.0f;
            out[o * 4 + 0] = clamp01(x1 * inv);
            out[o * 4 + 1] = clamp01(y1 * inv);
            out[o * 4 + 2] = clamp01(x2 * inv);
            out[o * 4 + 3] = clamp01(y2 * inv);
            out[12000 + o] = score;
            out[15000 + o] = (float)lbl;
            float off = (float)lbl * 8192.0f;    // 4 * IMG_W (cross-class separation)
            g_lkey[l * 1024 + t] = ((u64)u << 32) | (0xFFFFFFFFu - (u32)o);
            g_nbox[o] = make_float4(x1 + off, y1 + off, x2 + off, y2 + off);
            g_nvalid[o] = (score >= 0.05f) ? 1 : 0;
        }
    }
    gbar();

    // ---------- Phase G: 3-way merge-by-rank (blocks 0-2) ----------
    if (bl < 3 && t < 1000) {
        int l = bl;
        u64 kg = g_lkey[l * 1024 + t];
        int r = t;
#pragma unroll
        for (int m = 0; m < 3; m++) {
            if (m == l) continue;
            const u64* arr = g_lkey + m * 1024;
            int lo = 0, hi = 1000;
            while (lo < hi) {
                int mid = (lo + hi) >> 1;
                if (arr[mid] > kg) lo = mid + 1; else hi = mid;
            }
            r += lo;
        }
        int o = l * 1000 + t;
        g_sorder[r] = o;
        float4 b = g_nbox[o];
        g_sbox[r] = b;
        g_sarea[r] = (b.z - b.x) * (b.w - b.y);
        if (g_nvalid[o]) atomicOr(&g_validw[r >> 6], 1ull << (r & 63));
    }
    gbar();

    // ---------- Phase H: suppression bitmask matrix (141 tiles over 128 blocks) ----------
    for (int tile = bl; tile < 141; tile += NBLK) {
        int cb = tile % 47, ch = tile / 47;
        __syncthreads();
        if (t < 64) {
            int j = cb * 64 + t;
            if (j < 3000) { s_cbx[t] = g_sbox[j]; s_car[t] = g_sarea[j]; }
            else          { s_cbx[t] = make_float4(1e30f, 1e30f, 1e30f, 1e30f); s_car[t] = 0.f; }
        }
        __syncthreads();
        int i = ch * 1024 + t;
        if (i < 3000) {
            if ((cb + 1) * 64 <= i) {
                g_supp[(size_t)i * 48 + cb] = 0ull;
            } else {
                float4 bi = g_sbox[i];
                float s = g_sarea[i] + 1e-14f;
                u64 mask = 0ull;
                if (cb * 64 > i) {
#pragma unroll 4
                    for (int jj = 0; jj < 64; jj++) {
                        float4 bj = s_cbx[jj];
                        float xx1 = fmaxf(bi.x, bj.x), yy1 = fmaxf(bi.y, bj.y);
                        float xx2 = fminf(bi.z, bj.z), yy2 = fminf(bi.w, bj.w);
                        float w = fmaxf(1e-10f, xx2 - xx1);
                        float h = fmaxf(1e-10f, yy2 - yy1);
                        float inter = w * h;
                        float u = (s + s_car[jj]) - inter;
                        if (inter > 0.6f * u) mask |= (1ull << jj);
                    }
                } else {
#pragma unroll 4
                    for (int jj = 0; jj < 64; jj++) {
                        float4 bj = s_cbx[jj];
                        float xx1 = fmaxf(bi.x, bj.x), yy1 = fmaxf(bi.y, bj.y);
                        float xx2 = fminf(bi.z, bj.z), yy2 = fminf(bi.w, bj.w);
                        float w = fmaxf(1e-10f, xx2 - xx1);
                        float h = fmaxf(1e-10f, yy2 - yy1);
                        float inter = w * h;
                        float u = (s + s_car[jj]) - inter;
                        if (inter > 0.6f * u && (cb * 64 + jj) > i) mask |= (1ull << jj);
                    }
                }
                g_supp[(size_t)i * 48 + cb] = mask;
            }
        }
    }
    gbar();

    // ---------- Phase I: block-parallel fixpoint greedy scan (block 0) ----------
    if (bl != 0) return;
    if (t < 48) s_rem[t] = ~g_validw[t];
    if (t < 48) g_validw[t] = 0ull;                 // clean for next replay
    // preload word-0 diagonal (warp 1)
    if (wid == 1) {
        s_diag[0][2 * lane]     = g_supp[(size_t)(2 * lane) * 48];
        s_diag[0][2 * lane + 1] = g_supp[(size_t)(2 * lane + 1) * 48];
    }
    __syncthreads();
    for (int w = 0; w < 47; w++) {
        // resolve word w (warp 0) + prefetch diag of w+1 (warp 1)
        if (wid == 1 && w + 1 < 47) {
            int ib = (w + 1) * 64 + 2 * lane;
            s_diag[(w + 1) & 1][2 * lane]     = g_supp[(size_t)ib * 48 + (w + 1)];
            s_diag[(w + 1) & 1][2 * lane + 1] = g_supp[(size_t)(ib + 1) * 48 + (w + 1)];
        }
        if (wid == 0) {
            u64 d0 = s_diag[w & 1][2 * lane];
            u64 d1 = s_diag[w & 1][2 * lane + 1];
            u64 base = ~s_rem[w];                   // candidate kept bits
            u64 K = base;
            // fixpoint: unique fixpoint == greedy serial result
            for (int iter = 0; iter < 64; iter++) {
                u64 vl = (((K >> (2 * lane)) & 1ull) ? d0 : 0ull) |
                         (((K >> (2 * lane + 1)) & 1ull) ? d1 : 0ull);
                // inclusive prefix-OR across lanes
                u64 p = vl;
#pragma unroll
                for (int off = 1; off < 32; off <<= 1) {
                    u32 lo = (u32)p, hi = (u32)(p >> 32);
                    u32 plo = __shfl_up_sync(FULLMASK, lo, off);
                    u32 phi = __shfl_up_sync(FULLMASK, hi, off);
                    if (lane >= off) p |= ((u64)phi << 32) | plo;
                }
                // exclusive prefix for this lane
                u32 elo = __shfl_up_sync(FULLMASK, (u32)p, 1);
                u32 ehi = __shfl_up_sync(FULLMASK, (u32)(p >> 32), 1);
                u64 ex = (lane == 0) ? 0ull : (((u64)ehi << 32) | elo);
                u64 Seven = ex;
                u64 Sodd  = ex | (((K >> (2 * lane)) & 1ull) ? d0 : 0ull);
                u64 nl = (((Seven >> (2 * lane)) & 1ull) << (2 * lane)) |
                         (((Sodd >> (2 * lane + 1)) & 1ull) << (2 * lane + 1));
                u64 newsup = warp_or(nl);
                u64 Kn = base & ~newsup;
                if (Kn == K) break;
                K = Kn;
            }
            if (lane == 0) s_kw[w] = K;
        }
        __syncthreads();
        // propagate kept rows into future words (all warps, parallel over f)
        u64 K = s_kw[w];
        for (int f = w + 1 + wid; f < 47; f += 32) {
            u64 val = 0ull;
            int i0 = w * 64 + 2 * lane;
            if ((K >> (2 * lane)) & 1ull)     val  = g_supp[(size_t)i0 * 48 + f];
            if ((K >> (2 * lane + 1)) & 1ull) val |= g_supp[(size_t)(i0 + 1) * 48 + f];
            val = warp_or(val);
            if (lane == 0) s_rem[f] |= val;
        }
        __syncthreads();
    }
    // ---------- Phase J: keep outputs ----------
    for (int r = t; r < 3000; r += NTHR) {
        int kept = (int)((s_kw[r >> 6] >> (r & 63)) & 1ull);
        out[18000 + g_sorder[r]] = kept ? 1.0f : 0.0f;
    }
}

// ---------------- launch ----------------
extern "C" void kernel_launch(void* const* d_in, const int* in_sizes, int n_in,
                              void* d_out, int out_size) {
    (void)in_sizes; (void)n_in; (void)out_size;
    const float* c0 = (const float*)d_in[0];
    const float* r0 = (const float*)d_in[1];
    const float* c1 = (const float*)d_in[2];
    const float* r1 = (const float*)d_in[3];
    const float* c2 = (const float*)d_in[4];
    const float* r2 = (const float*)d_in[5];
    const float* sc = (const float*)d_in[6];
    float* out = (float*)d_out;

    k_all<<<NBLK, NTHR>>>(c0, r0, c1, r1, c2, r2, sc, out);
}